// round 14
// baseline (speedup 1.0000x reference)
#include <cuda_runtime.h>
#include <cuda_bf16.h>
#include <math.h>
#include <stdint.h>

#define Bn   4
#define Tn   256
#define Vn   1024
#define Sn   64
#define DIMn 1024
#define CVn  256
#define BT   (Bn*Tn)          // 1024
#define SW   72               // smem word stride (conflict-free fragment LDS)

// ---------------- scratch ----------------
__device__ float    g_pp[2][4][CVn*DIMn];     // k1 split-K partials (fp32)
__device__ uint32_t g_Wuk16[CVn*DIMn/2];      // bf16x2
__device__ uint32_t g_Wuv16[CVn*DIMn/2];
__device__ float    g_bias_part[2][16][DIMn];
__device__ float    g_buk[DIMn];
__device__ float    g_buv[DIMn];
__device__ int      g_idx[BT*Sn];
__device__ float    g_Ppart[4][BT*CVn];       // k2b split-K partials (fp32)
__device__ uint32_t g_vis16[Bn*Vn*CVn/2];     // bf16x2 vision
__device__ uint32_t g_x16[BT*DIMn/2];         // bf16x2 x
__device__ uint32_t g_wp16[BT*CVn/2];         // bf16x2 wp
__device__ float    g_alpha[BT];

// ---------------- bf16 helpers ----------------
__device__ __forceinline__ uint32_t packbf(float x, float y) {
    __nv_bfloat162 h = __floats2bfloat162_rn(x, y);
    return *reinterpret_cast<uint32_t*>(&h);
}
__device__ __forceinline__ __nv_bfloat162 asbf2(uint32_t u) {
    return *reinterpret_cast<const __nv_bfloat162*>(&u);
}
__device__ __forceinline__ void mma_bf16(float c[4], const uint32_t a[4], const uint32_t b[2]) {
    asm volatile("mma.sync.aligned.m16n8k16.row.col.f32.bf16.bf16.f32 "
        "{%0,%1,%2,%3}, {%4,%5,%6,%7}, {%8,%9}, {%0,%1,%2,%3};"
        : "+f"(c[0]), "+f"(c[1]), "+f"(c[2]), "+f"(c[3])
        : "r"(a[0]), "r"(a[1]), "r"(a[2]), "r"(a[3]), "r"(b[0]), "r"(b[1]));
}

// ---------------- shared 64x64 mainloop ----------------
__device__ __forceinline__ void mma_tile_loop(
    int buf, int wm, int wn, int lane,
    uint32_t Ap[2][8][SW], uint32_t Bp[2][8][SW], float acc[2][4][4])
{
    uint32_t af[2][4], bfr[4][2];
    #pragma unroll
    for (int mi = 0; mi < 2; mi++) {
        const int row = wm + mi*16 + (lane >> 2);
        af[mi][0] = Ap[buf][    (lane & 3)][row];
        af[mi][1] = Ap[buf][    (lane & 3)][row + 8];
        af[mi][2] = Ap[buf][4 + (lane & 3)][row];
        af[mi][3] = Ap[buf][4 + (lane & 3)][row + 8];
    }
    #pragma unroll
    for (int ni = 0; ni < 4; ni++) {
        const int col = wn + ni*8 + (lane >> 2);
        bfr[ni][0] = Bp[buf][    (lane & 3)][col];
        bfr[ni][1] = Bp[buf][4 + (lane & 3)][col];
    }
    #pragma unroll
    for (int mi = 0; mi < 2; mi++)
        #pragma unroll
        for (int ni = 0; ni < 4; ni++)
            mma_bf16(acc[mi][ni], af[mi], bfr[ni]);
}

// ---------------- fp32-operand GEMM (k1 split-K), 64x64 tile, fp32 out ----------------
template<int Nn, int Ks>
__device__ __forceinline__ void gemm_f32(
    const int m0, const int n0, const int k0, const int ksub,
    const float* __restrict__ A, const float* __restrict__ Bm,
    float* __restrict__ C,
    uint32_t Ap[2][8][SW], uint32_t Bp[2][8][SW])
{
    const int tid = threadIdx.x, lane = tid & 31, wid = tid >> 5;
    const int wm = (wid & 1) * 32, wn = (wid >> 1) * 32;
    const int am0 = tid >> 2,         ag0 = tid & 3;
    const int am1 = (tid + 128) >> 2, ag1 = (tid + 128) & 3;
    const int bk2 = tid >> 4,         bng = tid & 15;

    float acc[2][4][4];
    #pragma unroll
    for (int i = 0; i < 2; i++)
        #pragma unroll
        for (int j = 0; j < 4; j++)
            #pragma unroll
            for (int q = 0; q < 4; q++) acc[i][j][q] = 0.f;

    float4 ra0, ra1, rb0, rb1;
    auto loadg = [&](int kt) {
        ra0 = *(const float4*)(A + (size_t)(m0 + am0)*Ks + k0 + kt + ag0*4);
        ra1 = *(const float4*)(A + (size_t)(m0 + am1)*Ks + k0 + kt + ag1*4);
        rb0 = *(const float4*)(Bm + (size_t)(k0 + kt + 2*bk2    )*Nn + n0 + bng*4);
        rb1 = *(const float4*)(Bm + (size_t)(k0 + kt + 2*bk2 + 1)*Nn + n0 + bng*4);
    };
    auto stores = [&](int buf) {
        Ap[buf][ag0*2    ][am0] = packbf(ra0.x, ra0.y);
        Ap[buf][ag0*2 + 1][am0] = packbf(ra0.z, ra0.w);
        Ap[buf][ag1*2    ][am1] = packbf(ra1.x, ra1.y);
        Ap[buf][ag1*2 + 1][am1] = packbf(ra1.z, ra1.w);
        uint4 q;
        q.x = packbf(rb0.x, rb1.x); q.y = packbf(rb0.y, rb1.y);
        q.z = packbf(rb0.z, rb1.z); q.w = packbf(rb0.w, rb1.w);
        *(uint4*)&Bp[buf][bk2][bng*4] = q;
    };

    loadg(0); stores(0); __syncthreads();
    const int niter = ksub >> 4;
    for (int it = 0; it < niter; it++) {
        const int buf = it & 1;
        const bool nxt = (it + 1 < niter);
        if (nxt) loadg((it + 1) << 4);
        mma_tile_loop(buf, wm, wn, lane, Ap, Bp, acc);
        if (nxt) { stores(buf ^ 1); __syncthreads(); }
    }

    #pragma unroll
    for (int mi = 0; mi < 2; mi++) {
        const int r = m0 + wm + mi*16 + (lane >> 2);
        #pragma unroll
        for (int ni = 0; ni < 4; ni++) {
            const int c = n0 + wn + ni*8 + 2*(lane & 3);
            float2 o0, o1;
            o0.x = acc[mi][ni][0]; o0.y = acc[mi][ni][1];
            o1.x = acc[mi][ni][2]; o1.y = acc[mi][ni][3];
            *(float2*)(C + (size_t)r*Nn + c) = o0;
            *(float2*)(C + (size_t)(r + 8)*Nn + c) = o1;
        }
    }
}

// ---------------- prep: k1 partials (512) + bias partials (32) + idx (1024) + converts (128) ----------------
__global__ void __launch_bounds__(128)
prep_kernel(const float* __restrict__ Wu, const float* __restrict__ Wk,
            const float* __restrict__ Wv, const float* __restrict__ bu,
            const void* __restrict__ maskp,
            const float* __restrict__ x, const float* __restrict__ vision) {
    __shared__ __align__(16) uint32_t Ap[2][8][SW];
    __shared__ __align__(16) uint32_t Bp[2][8][SW];
    const int bid = blockIdx.x;
    const int tid = threadIdx.x;

    if (bid < 512) {
        const int z = bid >> 8, r = bid & 255;
        const int ks = r >> 6, t = r & 63;
        const int m0 = (t >> 4) * 64, n0 = (t & 15) * 64;
        gemm_f32<DIMn, DIMn>(m0, n0, ks*256, 256, Wu, z ? Wv : Wk,
                             g_pp[z][ks], Ap, Bp);
    } else if (bid < 544) {
        const int r = bid - 512;
        const int z = r & 1, slice = r >> 1;
        const float* W = z ? Wv : Wk;
        const int d0 = slice * 64;
        __shared__ float sbu[64];
        if (tid < 64) sbu[tid] = bu[d0 + tid];
        __syncthreads();
        float acc[8];
        #pragma unroll
        for (int k = 0; k < 8; k++) acc[k] = 0.f;
        for (int dd = 0; dd < 64; dd++) {
            const float bv = sbu[dd];
            const float* row = W + (size_t)(d0 + dd)*DIMn + tid;
            #pragma unroll
            for (int k = 0; k < 8; k++) acc[k] += bv * row[128*k];
        }
        #pragma unroll
        for (int k = 0; k < 8; k++) g_bias_part[z][slice][tid + 128*k] = acc[k];
    } else if (bid < 1568) {
        const int bt = bid - 544, b = bt >> 8, t = bt & 255;
        const int lane = tid & 31, wid = tid >> 5;
        const unsigned char* m8 = (const unsigned char*)maskp;
        const int* m32 = (const int*)maskp;

        int dsum = 0;
        #pragma unroll
        for (int u = 0; u < 8; u++) dsum += (m8[(tid*8 + u)*4 + 1] != 0);
        const bool u8 = (__syncthreads_or(dsum) != 0);

        int flags = 0, cnt = 0;
        #pragma unroll
        for (int u = 0; u < 8; u++) {
            const int v = tid*8 + u;
            const int e = (b*Vn + v)*Tn + t;
            const int mm = u8 ? (int)m8[e] : (m32[e] != 0);
            if (mm) { flags |= (1 << u); cnt++; }
        }
        int val = cnt;
        #pragma unroll
        for (int off = 1; off < 32; off <<= 1) {
            int vv = __shfl_up_sync(0xffffffffu, val, off);
            if (lane >= off) val += vv;
        }
        __shared__ int wtot[4];
        if (lane == 31) wtot[wid] = val;
        __syncthreads();
        int woff = 0, total = 0;
        #pragma unroll
        for (int w = 0; w < 4; w++) { int tw = wtot[w]; if (w < wid) woff += tw; total += tw; }
        int pos = woff + val - cnt;
        #pragma unroll
        for (int u = 0; u < 8; u++)
            if (flags & (1 << u)) { if (pos < Sn) g_idx[bt*Sn + pos] = tid*8 + u; pos++; }
        if (tid == 0)
            for (int p = total; p < Sn; p++) g_idx[bt*Sn + p] = Vn;
    } else {
        const int r = bid - 1568;
        const bool isv = (r < 64);
        const int j = isv ? r : r - 64;
        const float2* src = (const float2*)(isv ? vision : x);
        uint32_t* dst = isv ? g_vis16 : g_x16;
        #pragma unroll
        for (int i = 0; i < 64; i++) {
            const int w = j*8192 + i*128 + tid;
            float2 v = src[w];
            dst[w] = packbf(v.x, v.y);
        }
    }
}

// ---------------- combine: Wuk16/Wuv16 from fp32 partials (512 blocks) ----------------
__global__ void __launch_bounds__(128)
combine_kernel() {
    const int bid = blockIdx.x, tid = threadIdx.x;
    #pragma unroll
    for (int h = 0; h < 2; h++) {
        const int F = bid*256 + h*128 + tid;
        const int z = F >> 16, off4 = F & 65535;
        float4 s = make_float4(0.f, 0.f, 0.f, 0.f);
        #pragma unroll
        for (int p = 0; p < 4; p++) {
            float4 v = ((const float4*)g_pp[z][p])[off4];
            s.x += v.x; s.y += v.y; s.z += v.z; s.w += v.w;
        }
        uint2 o; o.x = packbf(s.x, s.y); o.y = packbf(s.z, s.w);
        ((uint2*)(z ? g_Wuv16 : g_Wuk16))[off4] = o;
    }
}

// ---------------- k2b: P partials, 32x64 tiles, split-K x4 (512) + bias combine (2) ----------------
__global__ void __launch_bounds__(128)
k2b_kernel() {
    __shared__ __align__(16) uint32_t Ap[2][8][SW];
    __shared__ __align__(16) uint32_t Bp[2][8][SW];
    const int bid = blockIdx.x, tid = threadIdx.x;
    if (bid < 512) {
        const int ks = bid >> 7, r = bid & 127;
        const int m0 = (r >> 2) * 32, n0 = (r & 3) * 64;
        const int k0 = ks * 256;
        const int lane = tid & 31, wid = tid >> 5;
        const int wm = (wid & 1) * 16, wn = (wid >> 1) * 32;
        const int am2 = tid >> 2, akg2 = tid & 3;   // A: 32 rows x 4 uint2 groups
        const int bm = tid >> 1,  bkg = tid & 1;    // B: 64 rows x 2 uint4 groups

        float acc[4][4];
        #pragma unroll
        for (int j = 0; j < 4; j++)
            #pragma unroll
            for (int q = 0; q < 4; q++) acc[j][q] = 0.f;

        uint2 qa; uint4 qb;
        auto loadg = [&](int kt) {
            qa = *(const uint2*)(g_x16 + (size_t)(m0 + am2)*(DIMn/2) + (k0 + kt)/2 + akg2*2);
            qb = *(const uint4*)(g_Wuk16 + (size_t)(n0 + bm)*(DIMn/2) + (k0 + kt)/2 + bkg*4);
        };
        auto stores = [&](int buf) {
            Ap[buf][akg2*2    ][am2] = qa.x;
            Ap[buf][akg2*2 + 1][am2] = qa.y;
            Bp[buf][bkg*4 + 0][bm] = qb.x;
            Bp[buf][bkg*4 + 1][bm] = qb.y;
            Bp[buf][bkg*4 + 2][bm] = qb.z;
            Bp[buf][bkg*4 + 3][bm] = qb.w;
        };

        loadg(0); stores(0); __syncthreads();
        const int niter = 256 >> 4;   // 16
        for (int it = 0; it < niter; it++) {
            const int buf = it & 1;
            const bool nxt = (it + 1 < niter);
            if (nxt) loadg((it + 1) << 4);

            uint32_t af[4], bfr[4][2];
            {
                const int row = wm + (lane >> 2);
                af[0] = Ap[buf][    (lane & 3)][row];
                af[1] = Ap[buf][    (lane & 3)][row + 8];
                af[2] = Ap[buf][4 + (lane & 3)][row];
                af[3] = Ap[buf][4 + (lane & 3)][row + 8];
            }
            #pragma unroll
            for (int ni = 0; ni < 4; ni++) {
                const int col = wn + ni*8 + (lane >> 2);
                bfr[ni][0] = Bp[buf][    (lane & 3)][col];
                bfr[ni][1] = Bp[buf][4 + (lane & 3)][col];
            }
            #pragma unroll
            for (int ni = 0; ni < 4; ni++)
                mma_bf16(acc[ni], af, bfr[ni]);

            if (nxt) { stores(buf ^ 1); __syncthreads(); }
        }

        {
            const int r2 = m0 + wm + (lane >> 2);
            float* C = g_Ppart[ks];
            #pragma unroll
            for (int ni = 0; ni < 4; ni++) {
                const int c = n0 + wn + ni*8 + 2*(lane & 3);
                float2 o0, o1;
                o0.x = acc[ni][0]; o0.y = acc[ni][1];
                o1.x = acc[ni][2]; o1.y = acc[ni][3];
                *(float2*)(C + (size_t)r2*CVn + c) = o0;
                *(float2*)(C + (size_t)(r2 + 8)*CVn + c) = o1;
            }
        }
    } else {
        const int z = bid - 512;
        #pragma unroll
        for (int h = 0; h < 8; h++) {
            const int j = h*128 + tid;
            float a = 0.f;
            #pragma unroll
            for (int p = 0; p < 16; p++) a += g_bias_part[z][p][j];
            (z ? g_buv : g_buk)[j] = a;
        }
    }
}

// ---------------- attn: fused gather+dot+wsum, 2x4 register prefetch ----------------
__global__ void __launch_bounds__(256)
attn_kernel(const float* __restrict__ x) {
    __shared__ float part_s[8][264];
    __shared__ int   idx_s[Sn];
    __shared__ float red_s[8];
    __shared__ float alpha_s[8];

    const int bt = blockIdx.x, b = bt >> 8, tid = threadIdx.x;
    const int lane = tid & 31, wid = tid >> 5;

    if (tid < Sn) idx_s[tid] = g_idx[bt*Sn + tid];

    // bq partials
    {
        float4 xv = *(const float4*)(x + (size_t)bt*DIMn + tid*4);
        float4 bv = *(const float4*)(g_buk + tid*4);
        float a = xv.x*bv.x + xv.y*bv.y + xv.z*bv.z + xv.w*bv.w;
        #pragma unroll
        for (int off = 16; off; off >>= 1) a += __shfl_down_sync(0xffffffffu, a, off);
        if (lane == 0) red_s[wid] = a;
    }

    // P: lane owns cols 8l..8l+7, combine 4 partials, pack to bf16x2
    uint32_t P2[4];
    {
        float Pr[8];
        #pragma unroll
        for (int i = 0; i < 8; i++) Pr[i] = 0.f;
        #pragma unroll
        for (int p = 0; p < 4; p++) {
            const float4* pp = (const float4*)(g_Ppart[p] + bt*CVn);
            float4 a0 = pp[2*lane], a1 = pp[2*lane + 1];
            Pr[0] += a0.x; Pr[1] += a0.y; Pr[2] += a0.z; Pr[3] += a0.w;
            Pr[4] += a1.x; Pr[5] += a1.y; Pr[6] += a1.z; Pr[7] += a1.w;
        }
        P2[0] = packbf(Pr[0], Pr[1]); P2[1] = packbf(Pr[2], Pr[3]);
        P2[2] = packbf(Pr[4], Pr[5]); P2[3] = packbf(Pr[6], Pr[7]);
    }
    __syncthreads();

    __nv_bfloat162 acc2[4];
    #pragma unroll
    for (int i = 0; i < 4; i++) acc2[i] = __floats2bfloat162_rn(0.f, 0.f);
    float ae = 0.f;

    // 2 groups of 4 prefetched rows: warp w owns row (g*4+p)*8 + w
    #pragma unroll
    for (int g = 0; g < 2; g++) {
        uint4 q[4]; int iv[4];
        #pragma unroll
        for (int p = 0; p < 4; p++) {
            const int r = (g*4 + p)*8 + wid;
            iv[p] = idx_s[r];
            q[p] = make_uint4(0u, 0u, 0u, 0u);
            if (iv[p] < Vn)
                q[p] = ((const uint4*)(g_vis16 + (size_t)(b*Vn + iv[p])*128))[lane];
        }
        #pragma unroll
        for (int p = 0; p < 4; p++) {
            __nv_bfloat162 d2 = __floats2bfloat162_rn(0.f, 0.f);
            d2 = __hfma2(asbf2(q[p].x), asbf2(P2[0]), d2);
            d2 = __hfma2(asbf2(q[p].y), asbf2(P2[1]), d2);
            d2 = __hfma2(asbf2(q[p].z), asbf2(P2[2]), d2);
            d2 = __hfma2(asbf2(q[p].w), asbf2(P2[3]), d2);
            float2 dd = __bfloat1622float2(d2);
            float d = dd.x + dd.y;
            #pragma unroll
            for (int off = 16; off; off >>= 1) d += __shfl_xor_sync(0xffffffffu, d, off);
            const float lp = d * 0.03125f + (iv[p] < Vn ? 0.f : 100.f);
            const float e = __expf(fminf(lp, 80.f));
            ae += e;
            const uint32_t e2 = packbf(e, e);
            acc2[0] = __hfma2(asbf2(e2), asbf2(q[p].x), acc2[0]);
            acc2[1] = __hfma2(asbf2(e2), asbf2(q[p].y), acc2[1]);
            acc2[2] = __hfma2(asbf2(e2), asbf2(q[p].z), acc2[2]);
            acc2[3] = __hfma2(asbf2(e2), asbf2(q[p].w), acc2[3]);
        }
    }

    // write per-warp partials: lane owns cols 8l..8l+7
    {
        float4 f0, f1;
        float2 t0 = __bfloat1622float2(acc2[0]);
        float2 t1 = __bfloat1622float2(acc2[1]);
        float2 t2 = __bfloat1622float2(acc2[2]);
        float2 t3 = __bfloat1622float2(acc2[3]);
        f0.x = t0.x; f0.y = t0.y; f0.z = t1.x; f0.w = t1.y;
        f1.x = t2.x; f1.y = t2.y; f1.z = t3.x; f1.w = t3.y;
        *(float4*)&part_s[wid][8*lane]     = f0;
        *(float4*)&part_s[wid][8*lane + 4] = f1;
        if (lane == 0) alpha_s[wid] = ae;
    }
    __syncthreads();

    const float bqv = red_s[0] + red_s[1] + red_s[2] + red_s[3]
                    + red_s[4] + red_s[5] + red_s[6] + red_s[7];
    const float f = __expf(bqv * 0.03125f);

    // final combine: thread owns column tid
    {
        float s = 0.f;
        #pragma unroll
        for (int w = 0; w < 8; w++) s += part_s[w][tid];
        s *= f;
        const float hi = __shfl_down_sync(0xffffffffu, s, 1);
        if ((tid & 1) == 0)
            g_wp16[bt*128 + (tid >> 1)] = packbf(s, hi);
    }

    if (tid == 0) {
        float a = 0.f;
        #pragma unroll
        for (int w = 0; w < 8; w++) a += alpha_s[w];
        g_alpha[bt] = a * f;
    }
}

// ---------------- k6: full-K, 32x64 tiles (512 blocks), fused Z/bias/residual ----------------
__global__ void __launch_bounds__(128)
k6_kernel(const float* __restrict__ x, float* __restrict__ out) {
    __shared__ __align__(16) uint32_t Ap[2][8][SW];
    __shared__ __align__(16) uint32_t Bp[2][8][SW];
    __shared__ float zr[4];
    const int tid = threadIdx.x, lane = tid & 31, wid = tid >> 5;
    const int m0 = (blockIdx.x >> 4) * 32, n0 = (blockIdx.x & 15) * 64;
    const int b = m0 >> 8;

    float a = g_alpha[b*256 + tid] + g_alpha[b*256 + 128 + tid];
    #pragma unroll
    for (int off = 16; off; off >>= 1) a += __shfl_down_sync(0xffffffffu, a, off);
    if (lane == 0) zr[wid] = a;
    __syncthreads();
    const float iz = 1.0f / (zr[0] + zr[1] + zr[2] + zr[3]);
    __syncthreads();

    const int wm = (wid & 1) * 16, wn = (wid >> 1) * 32;
    const int am = tid >> 2, akg = tid & 3;
    const int bk2 = tid >> 4, bn4 = (tid & 15) * 4;

    float acc[4][4];
    #pragma unroll
    for (int j = 0; j < 4; j++)
        #pragma unroll
        for (int q = 0; q < 4; q++) acc[j][q] = 0.f;

    uint2 qa, rb0, rb1;
    auto loadg = [&](int kt) {
        qa  = *(const uint2*)(g_wp16 + (size_t)(m0 + am)*(CVn/2) + kt/2 + akg*2);
        rb0 = *(const uint2*)(g_Wuv16 + (size_t)(kt + 2*bk2    )*(DIMn/2) + (n0 + bn4)/2);
        rb1 = *(const uint2*)(g_Wuv16 + (size_t)(kt + 2*bk2 + 1)*(DIMn/2) + (n0 + bn4)/2);
    };
    auto stores = [&](int buf) {
        Ap[buf][akg*2    ][am] = qa.x;
        Ap[buf][akg*2 + 1][am] = qa.y;
        uint4 q;
        q.x = __byte_perm(rb0.x, rb1.x, 0x5410);
        q.y = __byte_perm(rb0.x, rb1.x, 0x7632);
        q.z = __byte_perm(rb0.y, rb1.y, 0x5410);
        q.w = __byte_perm(rb0.y, rb1.y, 0x7632);
        *(uint4*)&Bp[buf][bk2][bn4] = q;
    };

    loadg(0); stores(0); __syncthreads();
    const int niter = CVn >> 4;
    for (int it = 0; it < niter; it++) {
        const int buf = it & 1;
        const bool nxt = (it + 1 < niter);
        if (nxt) loadg((it + 1) << 4);

        uint32_t af[4], bfr[4][2];
        {
            const int row = wm + (lane >> 2);
            af[0] = Ap[buf][    (lane & 3)][row];
            af[1] = Ap[buf][    (lane & 3)][row + 8];
            af[2] = Ap[buf][4 + (lane & 3)][row];
            af[3] = Ap[buf][4 + (lane & 3)][row + 8];
        }
        #pragma unroll
        for (int ni = 0; ni < 4; ni++) {
            const int col = wn + ni*8 + (lane >> 2);
            bfr[ni][0] = Bp[buf][    (lane & 3)][col];
            bfr[ni][1] = Bp[buf][4 + (lane & 3)][col];
        }
        #pragma unroll
        for (int ni = 0; ni < 4; ni++)
            mma_bf16(acc[ni], af, bfr[ni]);

        if (nxt) { stores(buf ^ 1); __syncthreads(); }
    }

    {
        const int r = m0 + wm + (lane >> 2);
        const float a0 = g_alpha[r], a1 = g_alpha[r + 8];
        #pragma unroll
        for (int ni = 0; ni < 4; ni++) {
            const int c = n0 + wn + ni*8 + 2*(lane & 3);
            float2 bv = *(const float2*)(g_buv + c);
            float2 x0 = *(const float2*)(x + (size_t)r*DIMn + c);
            float2 x1 = *(const float2*)(x + (size_t)(r + 8)*DIMn + c);
            float2 o0, o1;
            o0.x = (acc[ni][0] + a0*bv.x)*iz + x0.x;
            o0.y = (acc[ni][1] + a0*bv.y)*iz + x0.y;
            o1.x = (acc[ni][2] + a1*bv.x)*iz + x1.x;
            o1.y = (acc[ni][3] + a1*bv.y)*iz + x1.y;
            *(float2*)(out + (size_t)r*DIMn + c) = o0;
            *(float2*)(out + (size_t)(r + 8)*DIMn + c) = o1;
        }
    }
}

// ---------------- launch ----------------
extern "C" void kernel_launch(void* const* d_in, const int* in_sizes, int n_in,
                              void* d_out, int out_size) {
    const float* x      = (const float*)d_in[0];
    const float* vision = (const float*)d_in[1];
    const void*  mask   = d_in[2];
    const float* Wu     = (const float*)d_in[3];
    const float* bu     = (const float*)d_in[4];
    const float* Wk     = (const float*)d_in[5];
    const float* Wv     = (const float*)d_in[6];
    float* out = (float*)d_out;

    prep_kernel<<<1568 + 128, 128>>>(Wu, Wk, Wv, bu, mask, x, vision);
    combine_kernel<<<512, 128>>>();
    k2b_kernel<<<514, 128>>>();
    attn_kernel<<<BT, 256>>>(x);
    k6_kernel<<<512, 128>>>(x, out);
}

// round 16
// speedup vs baseline: 1.0411x; 1.0411x over previous
#include <cuda_runtime.h>
#include <cuda_bf16.h>
#include <math.h>
#include <stdint.h>

#define Bn   4
#define Tn   256
#define Vn   1024
#define Sn   64
#define DIMn 1024
#define CVn  256
#define BT   (Bn*Tn)          // 1024
#define SW   72               // smem word stride (conflict-free fragment LDS)

// ---------------- scratch ----------------
__device__ float    g_pp[2][4][CVn*DIMn];     // k1 split-K partials (fp32)
__device__ uint32_t g_Wuk16[CVn*DIMn/2];      // bf16x2
__device__ uint32_t g_Wuv16[CVn*DIMn/2];
__device__ float    g_bias_part[2][16][DIMn];
__device__ float    g_buk[DIMn];
__device__ float    g_buv[DIMn];
__device__ int      g_idx[BT*Sn];
__device__ float    g_Ppart[4][BT*CVn];       // k2b split-K partials (fp32)
__device__ uint32_t g_vis16[Bn*Vn*CVn/2];     // bf16x2 vision
__device__ uint32_t g_x16[BT*DIMn/2];         // bf16x2 x
__device__ uint32_t g_wp16[BT*CVn/2];         // bf16x2 wp
__device__ float    g_alpha[BT];

// ---------------- bf16 helpers ----------------
__device__ __forceinline__ uint32_t packbf(float x, float y) {
    __nv_bfloat162 h = __floats2bfloat162_rn(x, y);
    return *reinterpret_cast<uint32_t*>(&h);
}
__device__ __forceinline__ __nv_bfloat162 asbf2(uint32_t u) {
    return *reinterpret_cast<const __nv_bfloat162*>(&u);
}
__device__ __forceinline__ void mma_bf16(float c[4], const uint32_t a[4], const uint32_t b[2]) {
    asm volatile("mma.sync.aligned.m16n8k16.row.col.f32.bf16.bf16.f32 "
        "{%0,%1,%2,%3}, {%4,%5,%6,%7}, {%8,%9}, {%0,%1,%2,%3};"
        : "+f"(c[0]), "+f"(c[1]), "+f"(c[2]), "+f"(c[3])
        : "r"(a[0]), "r"(a[1]), "r"(a[2]), "r"(a[3]), "r"(b[0]), "r"(b[1]));
}

// ---------------- shared 64x64 mainloop ----------------
__device__ __forceinline__ void mma_tile_loop(
    int buf, int wm, int wn, int lane,
    uint32_t Ap[2][8][SW], uint32_t Bp[2][8][SW], float acc[2][4][4])
{
    uint32_t af[2][4], bfr[4][2];
    #pragma unroll
    for (int mi = 0; mi < 2; mi++) {
        const int row = wm + mi*16 + (lane >> 2);
        af[mi][0] = Ap[buf][    (lane & 3)][row];
        af[mi][1] = Ap[buf][    (lane & 3)][row + 8];
        af[mi][2] = Ap[buf][4 + (lane & 3)][row];
        af[mi][3] = Ap[buf][4 + (lane & 3)][row + 8];
    }
    #pragma unroll
    for (int ni = 0; ni < 4; ni++) {
        const int col = wn + ni*8 + (lane >> 2);
        bfr[ni][0] = Bp[buf][    (lane & 3)][col];
        bfr[ni][1] = Bp[buf][4 + (lane & 3)][col];
    }
    #pragma unroll
    for (int mi = 0; mi < 2; mi++)
        #pragma unroll
        for (int ni = 0; ni < 4; ni++)
            mma_bf16(acc[mi][ni], af[mi], bfr[ni]);
}

// ---------------- fp32-operand GEMM (k1 split-K), 64x64 tile, fp32 out ----------------
template<int Nn, int Ks>
__device__ __forceinline__ void gemm_f32(
    const int m0, const int n0, const int k0, const int ksub,
    const float* __restrict__ A, const float* __restrict__ Bm,
    float* __restrict__ C,
    uint32_t Ap[2][8][SW], uint32_t Bp[2][8][SW])
{
    const int tid = threadIdx.x, lane = tid & 31, wid = tid >> 5;
    const int wm = (wid & 1) * 32, wn = (wid >> 1) * 32;
    const int am0 = tid >> 2,         ag0 = tid & 3;
    const int am1 = (tid + 128) >> 2, ag1 = (tid + 128) & 3;
    const int bk2 = tid >> 4,         bng = tid & 15;

    float acc[2][4][4];
    #pragma unroll
    for (int i = 0; i < 2; i++)
        #pragma unroll
        for (int j = 0; j < 4; j++)
            #pragma unroll
            for (int q = 0; q < 4; q++) acc[i][j][q] = 0.f;

    float4 ra0, ra1, rb0, rb1;
    auto loadg = [&](int kt) {
        ra0 = *(const float4*)(A + (size_t)(m0 + am0)*Ks + k0 + kt + ag0*4);
        ra1 = *(const float4*)(A + (size_t)(m0 + am1)*Ks + k0 + kt + ag1*4);
        rb0 = *(const float4*)(Bm + (size_t)(k0 + kt + 2*bk2    )*Nn + n0 + bng*4);
        rb1 = *(const float4*)(Bm + (size_t)(k0 + kt + 2*bk2 + 1)*Nn + n0 + bng*4);
    };
    auto stores = [&](int buf) {
        Ap[buf][ag0*2    ][am0] = packbf(ra0.x, ra0.y);
        Ap[buf][ag0*2 + 1][am0] = packbf(ra0.z, ra0.w);
        Ap[buf][ag1*2    ][am1] = packbf(ra1.x, ra1.y);
        Ap[buf][ag1*2 + 1][am1] = packbf(ra1.z, ra1.w);
        uint4 q;
        q.x = packbf(rb0.x, rb1.x); q.y = packbf(rb0.y, rb1.y);
        q.z = packbf(rb0.z, rb1.z); q.w = packbf(rb0.w, rb1.w);
        *(uint4*)&Bp[buf][bk2][bng*4] = q;
    };

    loadg(0); stores(0); __syncthreads();
    const int niter = ksub >> 4;
    for (int it = 0; it < niter; it++) {
        const int buf = it & 1;
        const bool nxt = (it + 1 < niter);
        if (nxt) loadg((it + 1) << 4);
        mma_tile_loop(buf, wm, wn, lane, Ap, Bp, acc);
        if (nxt) { stores(buf ^ 1); __syncthreads(); }
    }

    #pragma unroll
    for (int mi = 0; mi < 2; mi++) {
        const int r = m0 + wm + mi*16 + (lane >> 2);
        #pragma unroll
        for (int ni = 0; ni < 4; ni++) {
            const int c = n0 + wn + ni*8 + 2*(lane & 3);
            float2 o0, o1;
            o0.x = acc[mi][ni][0]; o0.y = acc[mi][ni][1];
            o1.x = acc[mi][ni][2]; o1.y = acc[mi][ni][3];
            *(float2*)(C + (size_t)r*Nn + c) = o0;
            *(float2*)(C + (size_t)(r + 8)*Nn + c) = o1;
        }
    }
}

// ---------------- bf16-operand GEMM 64x64 tile (k2b), fp32 out ----------------
template<int Nn, int Ks>
__device__ __forceinline__ void gemm_1616_tb(
    const int m0, const int n0, const int k0, const int ksub,
    const uint32_t* __restrict__ A16, const uint32_t* __restrict__ B16,
    float* __restrict__ C,
    uint32_t Ap[2][8][SW], uint32_t Bp[2][8][SW])
{
    const int tid = threadIdx.x, lane = tid & 31, wid = tid >> 5;
    const int wm = (wid & 1) * 32, wn = (wid >> 1) * 32;
    const int am = tid >> 1, akg = tid & 1;

    float acc[2][4][4];
    #pragma unroll
    for (int i = 0; i < 2; i++)
        #pragma unroll
        for (int j = 0; j < 4; j++)
            #pragma unroll
            for (int q = 0; q < 4; q++) acc[i][j][q] = 0.f;

    uint4 qa, qb;
    auto loadg = [&](int kt) {
        qa = *(const uint4*)(A16 + (size_t)(m0 + am)*(Ks/2) + (k0 + kt)/2 + akg*4);
        qb = *(const uint4*)(B16 + (size_t)(n0 + am)*(Ks/2) + (k0 + kt)/2 + akg*4);
    };
    auto stores = [&](int buf) {
        Ap[buf][akg*4 + 0][am] = qa.x;
        Ap[buf][akg*4 + 1][am] = qa.y;
        Ap[buf][akg*4 + 2][am] = qa.z;
        Ap[buf][akg*4 + 3][am] = qa.w;
        Bp[buf][akg*4 + 0][am] = qb.x;
        Bp[buf][akg*4 + 1][am] = qb.y;
        Bp[buf][akg*4 + 2][am] = qb.z;
        Bp[buf][akg*4 + 3][am] = qb.w;
    };

    loadg(0); stores(0); __syncthreads();
    const int niter = ksub >> 4;
    for (int it = 0; it < niter; it++) {
        const int buf = it & 1;
        const bool nxt = (it + 1 < niter);
        if (nxt) loadg((it + 1) << 4);
        mma_tile_loop(buf, wm, wn, lane, Ap, Bp, acc);
        if (nxt) { stores(buf ^ 1); __syncthreads(); }
    }

    #pragma unroll
    for (int mi = 0; mi < 2; mi++) {
        const int r = m0 + wm + mi*16 + (lane >> 2);
        #pragma unroll
        for (int ni = 0; ni < 4; ni++) {
            const int c = n0 + wn + ni*8 + 2*(lane & 3);
            float2 o0, o1;
            o0.x = acc[mi][ni][0]; o0.y = acc[mi][ni][1];
            o1.x = acc[mi][ni][2]; o1.y = acc[mi][ni][3];
            *(float2*)(C + (size_t)r*Nn + c) = o0;
            *(float2*)(C + (size_t)(r + 8)*Nn + c) = o1;
        }
    }
}

// ---------------- prep: k1 partials (512) + bias partials (32) + idx (1024) + converts (128) ----------------
__global__ void __launch_bounds__(128)
prep_kernel(const float* __restrict__ Wu, const float* __restrict__ Wk,
            const float* __restrict__ Wv, const float* __restrict__ bu,
            const void* __restrict__ maskp,
            const float* __restrict__ x, const float* __restrict__ vision) {
    __shared__ __align__(16) uint32_t Ap[2][8][SW];
    __shared__ __align__(16) uint32_t Bp[2][8][SW];
    const int bid = blockIdx.x;
    const int tid = threadIdx.x;

    if (bid < 512) {
        const int z = bid >> 8, r = bid & 255;
        const int ks = r >> 6, t = r & 63;
        const int m0 = (t >> 4) * 64, n0 = (t & 15) * 64;
        gemm_f32<DIMn, DIMn>(m0, n0, ks*256, 256, Wu, z ? Wv : Wk,
                             g_pp[z][ks], Ap, Bp);
    } else if (bid < 544) {
        const int r = bid - 512;
        const int z = r & 1, slice = r >> 1;
        const float* W = z ? Wv : Wk;
        const int d0 = slice * 64;
        __shared__ float sbu[64];
        if (tid < 64) sbu[tid] = bu[d0 + tid];
        __syncthreads();
        float acc[8];
        #pragma unroll
        for (int k = 0; k < 8; k++) acc[k] = 0.f;
        for (int dd = 0; dd < 64; dd++) {
            const float bv = sbu[dd];
            const float* row = W + (size_t)(d0 + dd)*DIMn + tid;
            #pragma unroll
            for (int k = 0; k < 8; k++) acc[k] += bv * row[128*k];
        }
        #pragma unroll
        for (int k = 0; k < 8; k++) g_bias_part[z][slice][tid + 128*k] = acc[k];
    } else if (bid < 1568) {
        const int bt = bid - 544, b = bt >> 8, t = bt & 255;
        const int lane = tid & 31, wid = tid >> 5;
        const unsigned char* m8 = (const unsigned char*)maskp;
        const int* m32 = (const int*)maskp;

        int dsum = 0;
        #pragma unroll
        for (int u = 0; u < 8; u++) dsum += (m8[(tid*8 + u)*4 + 1] != 0);
        const bool u8 = (__syncthreads_or(dsum) != 0);

        int flags = 0, cnt = 0;
        #pragma unroll
        for (int u = 0; u < 8; u++) {
            const int v = tid*8 + u;
            const int e = (b*Vn + v)*Tn + t;
            const int mm = u8 ? (int)m8[e] : (m32[e] != 0);
            if (mm) { flags |= (1 << u); cnt++; }
        }
        int val = cnt;
        #pragma unroll
        for (int off = 1; off < 32; off <<= 1) {
            int vv = __shfl_up_sync(0xffffffffu, val, off);
            if (lane >= off) val += vv;
        }
        __shared__ int wtot[4];
        if (lane == 31) wtot[wid] = val;
        __syncthreads();
        int woff = 0, total = 0;
        #pragma unroll
        for (int w = 0; w < 4; w++) { int tw = wtot[w]; if (w < wid) woff += tw; total += tw; }
        int pos = woff + val - cnt;
        #pragma unroll
        for (int u = 0; u < 8; u++)
            if (flags & (1 << u)) { if (pos < Sn) g_idx[bt*Sn + pos] = tid*8 + u; pos++; }
        if (tid == 0)
            for (int p = total; p < Sn; p++) g_idx[bt*Sn + p] = Vn;
    } else {
        const int r = bid - 1568;
        const bool isv = (r < 64);
        const int j = isv ? r : r - 64;
        const float2* src = (const float2*)(isv ? vision : x);
        uint32_t* dst = isv ? g_vis16 : g_x16;
        #pragma unroll
        for (int i = 0; i < 64; i++) {
            const int w = j*8192 + i*128 + tid;
            float2 v = src[w];
            dst[w] = packbf(v.x, v.y);
        }
    }
}

// ---------------- combine: Wuk16/Wuv16 from fp32 partials (512 blocks) ----------------
__global__ void __launch_bounds__(128)
combine_kernel() {
    const int bid = blockIdx.x, tid = threadIdx.x;
    #pragma unroll
    for (int h = 0; h < 2; h++) {
        const int F = bid*256 + h*128 + tid;
        const int z = F >> 16, off4 = F & 65535;
        float4 s = make_float4(0.f, 0.f, 0.f, 0.f);
        #pragma unroll
        for (int p = 0; p < 4; p++) {
            float4 v = ((const float4*)g_pp[z][p])[off4];
            s.x += v.x; s.y += v.y; s.z += v.z; s.w += v.w;
        }
        uint2 o; o.x = packbf(s.x, s.y); o.y = packbf(s.z, s.w);
        ((uint2*)(z ? g_Wuv16 : g_Wuk16))[off4] = o;
    }
}

// ---------------- k2b: P partials split-K x4 (256, 64x64 tiles) + bias combine (2) ----------------
__global__ void __launch_bounds__(128)
k2b_kernel() {
    __shared__ __align__(16) uint32_t Ap[2][8][SW];
    __shared__ __align__(16) uint32_t Bp[2][8][SW];
    const int bid = blockIdx.x, tid = threadIdx.x;
    if (bid < 256) {
        const int ks = bid >> 6, r = bid & 63;
        const int m0 = (r >> 2) * 64, n0 = (r & 3) * 64;
        gemm_1616_tb<CVn, DIMn>(m0, n0, ks*256, 256, g_x16, g_Wuk16,
                                g_Ppart[ks], Ap, Bp);
    } else {
        const int z = bid - 256;
        #pragma unroll
        for (int h = 0; h < 8; h++) {
            const int j = h*128 + tid;
            float a = 0.f;
            #pragma unroll
            for (int p = 0; p < 16; p++) a += g_bias_part[z][p][j];
            (z ? g_buv : g_buk)[j] = a;
        }
    }
}

// ---------------- attn: fused gather+dot+wsum, 8-row register prefetch ----------------
__global__ void __launch_bounds__(256)
attn_kernel(const float* __restrict__ x) {
    __shared__ float part_s[8][264];
    __shared__ int   idx_s[Sn];
    __shared__ float red_s[8];
    __shared__ float alpha_s[8];

    const int bt = blockIdx.x, b = bt >> 8, tid = threadIdx.x;
    const int lane = tid & 31, wid = tid >> 5;

    if (tid < Sn) idx_s[tid] = g_idx[bt*Sn + tid];

    // bq partials
    {
        float4 xv = *(const float4*)(x + (size_t)bt*DIMn + tid*4);
        float4 bv = *(const float4*)(g_buk + tid*4);
        float a = xv.x*bv.x + xv.y*bv.y + xv.z*bv.z + xv.w*bv.w;
        #pragma unroll
        for (int off = 16; off; off >>= 1) a += __shfl_down_sync(0xffffffffu, a, off);
        if (lane == 0) red_s[wid] = a;
    }

    // P: lane owns cols 8l..8l+7, combine 4 partials, pack to bf16x2
    uint32_t P2[4];
    {
        float Pr[8];
        #pragma unroll
        for (int i = 0; i < 8; i++) Pr[i] = 0.f;
        #pragma unroll
        for (int p = 0; p < 4; p++) {
            const float4* pp = (const float4*)(g_Ppart[p] + bt*CVn);
            float4 a0 = pp[2*lane], a1 = pp[2*lane + 1];
            Pr[0] += a0.x; Pr[1] += a0.y; Pr[2] += a0.z; Pr[3] += a0.w;
            Pr[4] += a1.x; Pr[5] += a1.y; Pr[6] += a1.z; Pr[7] += a1.w;
        }
        P2[0] = packbf(Pr[0], Pr[1]); P2[1] = packbf(Pr[2], Pr[3]);
        P2[2] = packbf(Pr[4], Pr[5]); P2[3] = packbf(Pr[6], Pr[7]);
    }
    __syncthreads();

    __nv_bfloat162 acc2[4];
    #pragma unroll
    for (int i = 0; i < 4; i++) acc2[i] = __floats2bfloat162_rn(0.f, 0.f);
    float ae = 0.f;

    // single group: all 8 rows prefetched (MLP=8); warp w owns row p*8 + w
    {
        uint4 q[8]; int iv[8];
        #pragma unroll
        for (int p = 0; p < 8; p++) {
            const int r = p*8 + wid;
            iv[p] = idx_s[r];
            q[p] = make_uint4(0u, 0u, 0u, 0u);
            if (iv[p] < Vn)
                q[p] = ((const uint4*)(g_vis16 + (size_t)(b*Vn + iv[p])*128))[lane];
        }
        #pragma unroll
        for (int p = 0; p < 8; p++) {
            __nv_bfloat162 d2 = __floats2bfloat162_rn(0.f, 0.f);
            d2 = __hfma2(asbf2(q[p].x), asbf2(P2[0]), d2);
            d2 = __hfma2(asbf2(q[p].y), asbf2(P2[1]), d2);
            d2 = __hfma2(asbf2(q[p].z), asbf2(P2[2]), d2);
            d2 = __hfma2(asbf2(q[p].w), asbf2(P2[3]), d2);
            float2 dd = __bfloat1622float2(d2);
            float d = dd.x + dd.y;
            #pragma unroll
            for (int off = 16; off; off >>= 1) d += __shfl_xor_sync(0xffffffffu, d, off);
            const float lp = d * 0.03125f + (iv[p] < Vn ? 0.f : 100.f);
            const float e = __expf(fminf(lp, 80.f));
            ae += e;
            const uint32_t e2 = packbf(e, e);
            acc2[0] = __hfma2(asbf2(e2), asbf2(q[p].x), acc2[0]);
            acc2[1] = __hfma2(asbf2(e2), asbf2(q[p].y), acc2[1]);
            acc2[2] = __hfma2(asbf2(e2), asbf2(q[p].z), acc2[2]);
            acc2[3] = __hfma2(asbf2(e2), asbf2(q[p].w), acc2[3]);
        }
    }

    // write per-warp partials: lane owns cols 8l..8l+7
    {
        float4 f0, f1;
        float2 t0 = __bfloat1622float2(acc2[0]);
        float2 t1 = __bfloat1622float2(acc2[1]);
        float2 t2 = __bfloat1622float2(acc2[2]);
        float2 t3 = __bfloat1622float2(acc2[3]);
        f0.x = t0.x; f0.y = t0.y; f0.z = t1.x; f0.w = t1.y;
        f1.x = t2.x; f1.y = t2.y; f1.z = t3.x; f1.w = t3.y;
        *(float4*)&part_s[wid][8*lane]     = f0;
        *(float4*)&part_s[wid][8*lane + 4] = f1;
        if (lane == 0) alpha_s[wid] = ae;
    }
    __syncthreads();

    const float bqv = red_s[0] + red_s[1] + red_s[2] + red_s[3]
                    + red_s[4] + red_s[5] + red_s[6] + red_s[7];
    const float f = __expf(bqv * 0.03125f);

    // final combine: thread owns column tid
    {
        float s = 0.f;
        #pragma unroll
        for (int w = 0; w < 8; w++) s += part_s[w][tid];
        s *= f;
        const float hi = __shfl_down_sync(0xffffffffu, s, 1);
        if ((tid & 1) == 0)
            g_wp16[bt*128 + (tid >> 1)] = packbf(s, hi);
    }

    if (tid == 0) {
        float a = 0.f;
        #pragma unroll
        for (int w = 0; w < 8; w++) a += alpha_s[w];
        g_alpha[bt] = a * f;
    }
}

// ---------------- k6: full-K, 32x64 tiles (512 blocks), fused Z/bias/residual ----------------
__global__ void __launch_bounds__(128)
k6_kernel(const float* __restrict__ x, float* __restrict__ out) {
    __shared__ __align__(16) uint32_t Ap[2][8][SW];
    __shared__ __align__(16) uint32_t Bp[2][8][SW];
    __shared__ float zr[4];
    const int tid = threadIdx.x, lane = tid & 31, wid = tid >> 5;
    const int m0 = (blockIdx.x >> 4) * 32, n0 = (blockIdx.x & 15) * 64;
    const int b = m0 >> 8;

    float a = g_alpha[b*256 + tid] + g_alpha[b*256 + 128 + tid];
    #pragma unroll
    for (int off = 16; off; off >>= 1) a += __shfl_down_sync(0xffffffffu, a, off);
    if (lane == 0) zr[wid] = a;
    __syncthreads();
    const float iz = 1.0f / (zr[0] + zr[1] + zr[2] + zr[3]);
    __syncthreads();

    const int wm = (wid & 1) * 16, wn = (wid >> 1) * 32;
    const int am = tid >> 2, akg = tid & 3;
    const int bk2 = tid >> 4, bn4 = (tid & 15) * 4;

    float acc[4][4];
    #pragma unroll
    for (int j = 0; j < 4; j++)
        #pragma unroll
        for (int q = 0; q < 4; q++) acc[j][q] = 0.f;

    uint2 qa, rb0, rb1;
    auto loadg = [&](int kt) {
        qa  = *(const uint2*)(g_wp16 + (size_t)(m0 + am)*(CVn/2) + kt/2 + akg*2);
        rb0 = *(const uint2*)(g_Wuv16 + (size_t)(kt + 2*bk2    )*(DIMn/2) + (n0 + bn4)/2);
        rb1 = *(const uint2*)(g_Wuv16 + (size_t)(kt + 2*bk2 + 1)*(DIMn/2) + (n0 + bn4)/2);
    };
    auto stores = [&](int buf) {
        Ap[buf][akg*2    ][am] = qa.x;
        Ap[buf][akg*2 + 1][am] = qa.y;
        uint4 q;
        q.x = __byte_perm(rb0.x, rb1.x, 0x5410);
        q.y = __byte_perm(rb0.x, rb1.x, 0x7632);
        q.z = __byte_perm(rb0.y, rb1.y, 0x5410);
        q.w = __byte_perm(rb0.y, rb1.y, 0x7632);
        *(uint4*)&Bp[buf][bk2][bn4] = q;
    };

    loadg(0); stores(0); __syncthreads();
    const int niter = CVn >> 4;
    for (int it = 0; it < niter; it++) {
        const int buf = it & 1;
        const bool nxt = (it + 1 < niter);
        if (nxt) loadg((it + 1) << 4);

        uint32_t af[4], bfr[4][2];
        {
            const int row = wm + (lane >> 2);
            af[0] = Ap[buf][    (lane & 3)][row];
            af[1] = Ap[buf][    (lane & 3)][row + 8];
            af[2] = Ap[buf][4 + (lane & 3)][row];
            af[3] = Ap[buf][4 + (lane & 3)][row + 8];
        }
        #pragma unroll
        for (int ni = 0; ni < 4; ni++) {
            const int col = wn + ni*8 + (lane >> 2);
            bfr[ni][0] = Bp[buf][    (lane & 3)][col];
            bfr[ni][1] = Bp[buf][4 + (lane & 3)][col];
        }
        #pragma unroll
        for (int ni = 0; ni < 4; ni++)
            mma_bf16(acc[ni], af, bfr[ni]);

        if (nxt) { stores(buf ^ 1); __syncthreads(); }
    }

    {
        const int r = m0 + wm + (lane >> 2);
        const float a0 = g_alpha[r], a1 = g_alpha[r + 8];
        #pragma unroll
        for (int ni = 0; ni < 4; ni++) {
            const int c = n0 + wn + ni*8 + 2*(lane & 3);
            float2 bv = *(const float2*)(g_buv + c);
            float2 x0 = *(const float2*)(x + (size_t)r*DIMn + c);
            float2 x1 = *(const float2*)(x + (size_t)(r + 8)*DIMn + c);
            float2 o0, o1;
            o0.x = (acc[ni][0] + a0*bv.x)*iz + x0.x;
            o0.y = (acc[ni][1] + a0*bv.y)*iz + x0.y;
            o1.x = (acc[ni][2] + a1*bv.x)*iz + x1.x;
            o1.y = (acc[ni][3] + a1*bv.y)*iz + x1.y;
            *(float2*)(out + (size_t)r*DIMn + c) = o0;
            *(float2*)(out + (size_t)(r + 8)*DIMn + c) = o1;
        }
    }
}

// ---------------- launch ----------------
extern "C" void kernel_launch(void* const* d_in, const int* in_sizes, int n_in,
                              void* d_out, int out_size) {
    const float* x      = (const float*)d_in[0];
    const float* vision = (const float*)d_in[1];
    const void*  mask   = d_in[2];
    const float* Wu     = (const float*)d_in[3];
    const float* bu     = (const float*)d_in[4];
    const float* Wk     = (const float*)d_in[5];
    const float* Wv     = (const float*)d_in[6];
    float* out = (float*)d_out;

    prep_kernel<<<1568 + 128, 128>>>(Wu, Wk, Wv, bu, mask, x, vision);
    combine_kernel<<<512, 128>>>();
    k2b_kernel<<<258, 128>>>();
    attn_kernel<<<BT, 256>>>(x);
    k6_kernel<<<512, 128>>>(x, out);
}